// round 7
// baseline (speedup 1.0000x reference)
#include <cuda_runtime.h>
#include <cuda_bf16.h>
#include <cstdint>

#define DI __device__ __forceinline__

// ---------------- scratch (static device globals; no runtime alloc) ----------------
__device__ __nv_bfloat16 g_Xh [2048u*4096u];
__device__ __nv_bfloat16 g_Xl [2048u*4096u];
__device__ __nv_bfloat16 g_Wth[6144u*4096u];   // [wq|wk|wv]^T rows: 0-4095 q, 4096-5119 k, 5120-6143 v
__device__ __nv_bfloat16 g_Wtl[6144u*4096u];
__device__ __nv_bfloat16 g_WOth[4096u*4096u];  // wo^T
__device__ __nv_bfloat16 g_WOtl[4096u*4096u];
__device__ float         g_QKV[2048u*6144u];   // fused projection out (fp32): Q|K|V
__device__ __nv_bfloat16 g_Qh [2048u*4096u];   // post-rope, pre-scaled
__device__ __nv_bfloat16 g_Ql [2048u*4096u];
__device__ __nv_bfloat16 g_Kh [2048u*1024u];
__device__ __nv_bfloat16 g_Kl [2048u*1024u];
__device__ __nv_bfloat16 g_Vh [2048u*1024u];
__device__ __nv_bfloat16 g_Vl [2048u*1024u];
__device__ __nv_bfloat16 g_AOh[2048u*4096u];
__device__ __nv_bfloat16 g_AOl[2048u*4096u];

// ---------------- helpers ----------------
DI uint32_t s_addr(const void* p){ return (uint32_t)__cvta_generic_to_shared(p); }

DI void ldm_x4(uint32_t a, uint32_t &r0, uint32_t &r1, uint32_t &r2, uint32_t &r3){
  asm volatile("ldmatrix.sync.aligned.m8n8.x4.shared.b16 {%0,%1,%2,%3}, [%4];\n"
               : "=r"(r0), "=r"(r1), "=r"(r2), "=r"(r3) : "r"(a));
}
DI void ldm_x4t(uint32_t a, uint32_t &r0, uint32_t &r1, uint32_t &r2, uint32_t &r3){
  asm volatile("ldmatrix.sync.aligned.m8n8.x4.trans.shared.b16 {%0,%1,%2,%3}, [%4];\n"
               : "=r"(r0), "=r"(r1), "=r"(r2), "=r"(r3) : "r"(a));
}
DI void mma_bf(float c[4], const uint32_t a[4], const uint32_t b[2]){
  asm volatile("mma.sync.aligned.m16n8k16.row.col.f32.bf16.bf16.f32 "
               "{%0,%1,%2,%3}, {%4,%5,%6,%7}, {%8,%9}, {%0,%1,%2,%3};\n"
               : "+f"(c[0]), "+f"(c[1]), "+f"(c[2]), "+f"(c[3])
               : "r"(a[0]), "r"(a[1]), "r"(a[2]), "r"(a[3]), "r"(b[0]), "r"(b[1]));
}
DI uint32_t pk2(__nv_bfloat16 a, __nv_bfloat16 b){
  __nv_bfloat162 t = __halves2bfloat162(a, b);
  return *reinterpret_cast<uint32_t*>(&t);
}
DI void split4(const float4 &v, uint32_t &h0, uint32_t &h1, uint32_t &l0, uint32_t &l1){
  __nv_bfloat16 hx = __float2bfloat16_rn(v.x);
  __nv_bfloat16 hy = __float2bfloat16_rn(v.y);
  __nv_bfloat16 hz = __float2bfloat16_rn(v.z);
  __nv_bfloat16 hw = __float2bfloat16_rn(v.w);
  h0 = pk2(hx, hy); h1 = pk2(hz, hw);
  l0 = pk2(__float2bfloat16_rn(v.x - __bfloat162float(hx)),
           __float2bfloat16_rn(v.y - __bfloat162float(hy)));
  l1 = pk2(__float2bfloat16_rn(v.z - __bfloat162float(hz)),
           __float2bfloat16_rn(v.w - __bfloat162float(hw)));
}
DI void split_pk(float x, float y, uint32_t &h, uint32_t &l){
  __nv_bfloat16 hx = __float2bfloat16_rn(x);
  __nv_bfloat16 hy = __float2bfloat16_rn(y);
  h = pk2(hx, hy);
  l = pk2(__float2bfloat16_rn(x - __bfloat162float(hx)),
          __float2bfloat16_rn(y - __bfloat162float(hy)));
}

// ---------------- async copy primitives ----------------
DI void cp16(uint32_t saddr, const void* gaddr){
  asm volatile("cp.async.cg.shared.global [%0], [%1], 16;" :: "r"(saddr), "l"(gaddr) : "memory");
}
DI void cp_commit(){ asm volatile("cp.async.commit_group;" ::: "memory"); }
DI void cp_wait1(){ asm volatile("cp.async.wait_group 1;" ::: "memory"); }

// =====================================================================
// conversion kernels
// =====================================================================
__global__ void conv_x(const float* __restrict__ x)
{
  int i = blockIdx.x*256 + threadIdx.x;
  float4 v = reinterpret_cast<const float4*>(x)[i];
  uint32_t h0,h1,l0,l1; split4(v, h0,h1,l0,l1);
  reinterpret_cast<uint32_t*>(g_Xh)[i*2]   = h0;
  reinterpret_cast<uint32_t*>(g_Xh)[i*2+1] = h1;
  reinterpret_cast<uint32_t*>(g_Xl)[i*2]   = l0;
  reinterpret_cast<uint32_t*>(g_Xl)[i*2+1] = l1;
}

// transpose + split: src fp32 [K,N] -> dst bf16 hi/lo [N,K]
__global__ void tconv(const float* __restrict__ src,
                      __nv_bfloat16* __restrict__ dh, __nv_bfloat16* __restrict__ dl,
                      int K, int N)
{
  __shared__ float t[32][33];
  const int tid = threadIdx.x, tx = tid & 31, ty = tid >> 5;
  const int n0 = blockIdx.x << 5, k0 = blockIdx.y << 5;
  #pragma unroll
  for (int j = 0; j < 4; j++)
    t[ty + 8*j][tx] = src[(size_t)(k0 + ty + 8*j)*N + n0 + tx];
  __syncthreads();
  #pragma unroll
  for (int j = 0; j < 4; j++){
    float v = t[tx][ty + 8*j];
    __nv_bfloat16 h = __float2bfloat16_rn(v);
    size_t idx = (size_t)(n0 + ty + 8*j)*K + k0 + tx;
    dh[idx] = h;
    dl[idx] = __float2bfloat16_rn(v - __bfloat162float(h));
  }
}

// =====================================================================
// GEMM: C[M,N] = A(hi+lo)[M,K] * B(hi+lo)[N,K]^T, bf16x3, fp32 acc.
// CTA tile 256x128x32, 256 threads = 8 warps (4m x 2n), warp tile 64x64.
// 3-stage cp.async ring. Rows: 32 bf16 (64 B) + 16 pad = 80 B (conflict-free).
// smem reads: 85 B/mma (vs 256 previously) -- crossbar no longer the limiter.
// =====================================================================
#define GROWB 80
#define APLANE (256*GROWB)         // 20480 B
#define BPLANE (128*GROWB)         // 10240 B
#define GSTG   (2*APLANE + 2*BPLANE)  // 61440 B
#define GEMM_SMEM (3*GSTG)         // 184320 B

__global__ void __launch_bounds__(256, 1) gemm_ca(
    const __nv_bfloat16* __restrict__ Ah, const __nv_bfloat16* __restrict__ Al,
    const __nv_bfloat16* __restrict__ Bh, const __nv_bfloat16* __restrict__ Bl,
    float* __restrict__ C, int N, int K)
{
  extern __shared__ char smem[];
  const uint32_t sb = s_addr(smem);
  const int tid = threadIdx.x, lane = tid & 31, warp = tid >> 5;
  const int wm = warp >> 1, wn = warp & 1;
  const int m0 = blockIdx.y * 256, n0 = blockIdx.x * 128;

  float acc[4][8][4];
  #pragma unroll
  for (int i = 0; i < 4; i++)
    #pragma unroll
    for (int j = 0; j < 8; j++)
      #pragma unroll
      for (int k = 0; k < 4; k++) acc[i][j][k] = 0.f;

  auto issue = [&](int t){
    const uint32_t s0 = sb + (uint32_t)(t % 3)*GSTG;
    const int kb = t << 5;
    #pragma unroll
    for (int i = 0; i < 8; i++){     // A: 2 planes x 256 rows x 4 chunks = 2048 ops
      int idx = i*256 + tid;
      int p = idx >> 10, r = (idx >> 2) & 255, c = idx & 3;
      const __nv_bfloat16* g = (p ? Al : Ah) + (size_t)(m0 + r)*K + kb + c*8;
      cp16(s0 + (uint32_t)p*APLANE + r*GROWB + c*16, g);
    }
    #pragma unroll
    for (int i = 0; i < 4; i++){     // B: 2 planes x 128 rows x 4 chunks = 1024 ops
      int idx = i*256 + tid;
      int p = idx >> 9, r = (idx >> 2) & 127, c = idx & 3;
      const __nv_bfloat16* g = (p ? Bl : Bh) + (size_t)(n0 + r)*K + kb + c*8;
      cp16(s0 + 2u*APLANE + (uint32_t)p*BPLANE + r*GROWB + c*16, g);
    }
  };

  const int T = K >> 5;
  issue(0); cp_commit();
  issue(1); cp_commit();

  for (int t = 0; t < T; t++){
    cp_wait1();
    __syncthreads();
    if (t + 2 < T) issue(t + 2);
    cp_commit();
    const uint32_t s0 = sb + (uint32_t)(t % 3)*GSTG;
    const uint32_t aH = s0, aL = s0 + APLANE, bH = s0 + 2u*APLANE, bL = s0 + 2u*APLANE + BPLANE;
    #pragma unroll
    for (int ks = 0; ks < 2; ks++){
      uint32_t ah[4][4], al[4][4];
      #pragma unroll
      for (int wmi = 0; wmi < 4; wmi++){
        uint32_t off = (uint32_t)(wm*64 + wmi*16 + (lane & 15))*GROWB + ks*32 + ((lane >> 4) << 4);
        ldm_x4(aH + off, ah[wmi][0], ah[wmi][1], ah[wmi][2], ah[wmi][3]);
        ldm_x4(aL + off, al[wmi][0], al[wmi][1], al[wmi][2], al[wmi][3]);
      }
      const int nr = wn*64 + (lane & 7) + ((lane >> 4) << 3);
      const uint32_t ccb = ks*32 + (((lane >> 3) & 1) << 4);
      #pragma unroll
      for (int g4 = 0; g4 < 4; g4++){
        uint32_t bh[2][2], bl[2][2];
        uint32_t off = (uint32_t)(nr + g4*16)*GROWB + ccb;
        ldm_x4(bH + off, bh[0][0], bh[0][1], bh[1][0], bh[1][1]);
        ldm_x4(bL + off, bl[0][0], bl[0][1], bl[1][0], bl[1][1]);
        // pass-major: 8 independent accumulators between reuses
        #pragma unroll
        for (int wmi = 0; wmi < 4; wmi++)
          #pragma unroll
          for (int j = 0; j < 2; j++) mma_bf(acc[wmi][g4*2 + j], ah[wmi], bh[j]);
        #pragma unroll
        for (int wmi = 0; wmi < 4; wmi++)
          #pragma unroll
          for (int j = 0; j < 2; j++) mma_bf(acc[wmi][g4*2 + j], ah[wmi], bl[j]);
        #pragma unroll
        for (int wmi = 0; wmi < 4; wmi++)
          #pragma unroll
          for (int j = 0; j < 2; j++) mma_bf(acc[wmi][g4*2 + j], al[wmi], bh[j]);
      }
    }
    __syncthreads();
  }

  const int g = lane >> 2, tq = lane & 3;
  #pragma unroll
  for (int wmi = 0; wmi < 4; wmi++){
    int r = m0 + wm*64 + wmi*16 + g;
    #pragma unroll
    for (int nt = 0; nt < 8; nt++){
      int c = n0 + wn*64 + nt*8 + tq*2;
      float2 v0 = make_float2(acc[wmi][nt][0], acc[wmi][nt][1]);
      float2 v1 = make_float2(acc[wmi][nt][2], acc[wmi][nt][3]);
      *reinterpret_cast<float2*>(C + (size_t)r*N + c)     = v0;
      *reinterpret_cast<float2*>(C + (size_t)(r+8)*N + c) = v1;
    }
  }
}

// =====================================================================
// RoPE + split: QKV fp32 -> Q/K/V bf16 hi/lo planes. Q pre-scaled.
// =====================================================================
__global__ void rope_split(const float* __restrict__ fc)
{
  const int QP = 2048*2048, KP = 2048*512;
  int idx = blockIdx.x*256 + threadIdx.x;
  if (idx < QP){
    int s = idx >> 11, j = idx & 2047;
    int i = j & 63;
    float c = fc[s*128 + 2*i], d = fc[s*128 + 2*i + 1];
    const float* p = g_QKV + (size_t)s*6144 + 2*j;
    float a = p[0], b = p[1];
    const float sc = 0.08838834764831845f;   // 128^-0.5
    uint32_t hh, ll;
    split_pk((a*c - b*d)*sc, (a*d + b*c)*sc, hh, ll);
    size_t off = (size_t)s*4096 + 2*j;
    *reinterpret_cast<uint32_t*>(&g_Qh[off]) = hh;
    *reinterpret_cast<uint32_t*>(&g_Ql[off]) = ll;
  } else if (idx < QP + KP){
    int k = idx - QP;
    int s = k >> 9, j = k & 511;
    int i = j & 63;
    float c = fc[s*128 + 2*i], d = fc[s*128 + 2*i + 1];
    const float* p = g_QKV + (size_t)s*6144 + 4096 + 2*j;
    float a = p[0], b = p[1];
    uint32_t hh, ll;
    split_pk(a*c - b*d, a*d + b*c, hh, ll);
    size_t off = (size_t)s*1024 + 2*j;
    *reinterpret_cast<uint32_t*>(&g_Kh[off]) = hh;
    *reinterpret_cast<uint32_t*>(&g_Kl[off]) = ll;
  } else {
    int k = idx - QP - KP;
    int s = k >> 9, j = k & 511;
    const float* p = g_QKV + (size_t)s*6144 + 5120 + 2*j;
    uint32_t hh, ll;
    split_pk(p[0], p[1], hh, ll);
    size_t off = (size_t)s*1024 + 2*j;
    *reinterpret_cast<uint32_t*>(&g_Vh[off]) = hh;
    *reinterpret_cast<uint32_t*>(&g_Vl[off]) = ll;
  }
}

// =====================================================================
// Causal flash attention. CTA = (128 q rows, 1 head), 8 warps x 16 rows.
// KV tiles of 64, 3-stage cp.async ring of bf16 planes. bf16x3 math.
// Row = 128 bf16 = 256 B + 16 pad = 272 B stride (17 x 16B -> conflict-free).
// =====================================================================
#define FROWB 272
#define FPLANE (64*FROWB)          // 17408 B
#define FSTAGE (4*FPLANE)          // 69632 B
#define FLASH_SMEM (3*FSTAGE)      // 208896 B

__global__ void __launch_bounds__(256) flash_kernel()
{
  extern __shared__ char smem[];
  const uint32_t sb = s_addr(smem);
  const int tid = threadIdx.x, lane = tid & 31, warp = tid >> 5;
  const int qt = 15 - blockIdx.x;            // heavy tiles first
  const int h = blockIdx.y;
  const int q0 = qt*128, kvh = h >> 2;
  const int g = lane >> 2, t4 = lane & 3;

  // ---- stage Q planes into ring buffer 0 (exactly FSTAGE bytes), then frags ----
  #pragma unroll
  for (int i = 0; i < 16; i++){
    int idx = i*256 + tid;
    int p = idx >> 11, r = (idx >> 4) & 127, c = idx & 15;
    const __nv_bfloat16* src = (p ? g_Ql : g_Qh) + (size_t)(q0 + r)*4096 + h*128 + c*8;
    *reinterpret_cast<uint4*>(smem + p*(128*FROWB) + r*FROWB + c*16) =
        *reinterpret_cast<const uint4*>(src);
  }
  __syncthreads();

  uint32_t qh[8][4], ql[8][4];
  {
    const uint32_t qH = sb, qL = sb + 128*FROWB;
    uint32_t rowb = (uint32_t)(warp*16 + (lane & 15))*FROWB + ((lane >> 4) << 4);
    #pragma unroll
    for (int kk = 0; kk < 8; kk++){
      ldm_x4(qH + rowb + kk*32, qh[kk][0], qh[kk][1], qh[kk][2], qh[kk][3]);
      ldm_x4(qL + rowb + kk*32, ql[kk][0], ql[kk][1], ql[kk][2], ql[kk][3]);
    }
  }
  __syncthreads();   // all Q reads done before cp.async reuses buffer 0

  float o[16][4];
  #pragma unroll
  for (int i = 0; i < 16; i++){ o[i][0]=0.f; o[i][1]=0.f; o[i][2]=0.f; o[i][3]=0.f; }
  float rm0 = -1e30f, rm1 = -1e30f;
  float rl0 = 0.f,    rl1 = 0.f;

  const int nkv = qt*2 + 2;

  auto issue = [&](int kt){
    const uint32_t s0 = sb + (uint32_t)(kt % 3)*FSTAGE;
    const int kv0 = kt*64;
    #pragma unroll
    for (int i = 0; i < 16; i++){
      int idx = i*256 + tid;
      int p = idx >> 10, r = (idx >> 4) & 63, c = idx & 15;
      const __nv_bfloat16* base = (p == 0) ? g_Kh : (p == 1) ? g_Kl : (p == 2) ? g_Vh : g_Vl;
      cp16(s0 + (uint32_t)p*FPLANE + r*FROWB + c*16,
           base + (size_t)(kv0 + r)*1024 + kvh*128 + c*8);
    }
  };

  issue(0); cp_commit();
  issue(1); cp_commit();

  for (int kvt = 0; kvt < nkv; kvt++){
    const int kv0 = kvt*64;
    cp_wait1();
    __syncthreads();
    if (kvt + 2 < nkv) issue(kvt + 2);   // prefetch BEFORE compute (3rd buffer free)
    cp_commit();
    const uint32_t s0 = sb + (uint32_t)(kvt % 3)*FSTAGE;
    const uint32_t kH = s0, kL = s0 + FPLANE, vH = s0 + 2u*FPLANE, vL = s0 + 3u*FPLANE;

    // ---- S = Q K^T ----
    float s[8][4];
    #pragma unroll
    for (int i = 0; i < 8; i++){ s[i][0]=0.f; s[i][1]=0.f; s[i][2]=0.f; s[i][3]=0.f; }
    {
      const int nr = (lane & 7) + ((lane >> 4) << 3);
      #pragma unroll
      for (int kk = 0; kk < 8; kk++){
        const uint32_t ccb = kk*32 + (((lane >> 3) & 1) << 4);
        #pragma unroll
        for (int g4 = 0; g4 < 4; g4++){
          uint32_t bh[2][2], bl[2][2];
          uint32_t off = (uint32_t)(g4*16 + nr)*FROWB + ccb;
          ldm_x4(kH + off, bh[0][0], bh[0][1], bh[1][0], bh[1][1]);
          ldm_x4(kL + off, bl[0][0], bl[0][1], bl[1][0], bl[1][1]);
          mma_bf(s[g4*2],     qh[kk], bh[0]);
          mma_bf(s[g4*2 + 1], qh[kk], bh[1]);
          mma_bf(s[g4*2],     qh[kk], bl[0]);
          mma_bf(s[g4*2 + 1], qh[kk], bl[1]);
          mma_bf(s[g4*2],     ql[kk], bh[0]);
          mma_bf(s[g4*2 + 1], ql[kk], bh[1]);
        }
      }
    }

    // ---- causal mask ----
    if (kv0 + 63 > q0 + warp*16){
      #pragma unroll
      for (int nt = 0; nt < 8; nt++){
        int kvb = kv0 + nt*8 + t4*2;
        #pragma unroll
        for (int j = 0; j < 4; j++){
          int kv = kvb + (j & 1);
          int rw = q0 + warp*16 + g + ((j >> 1) << 3);
          if (kv > rw) s[nt][j] = -1e30f;
        }
      }
    }

    // ---- online softmax ----
    float mt0 = -1e30f, mt1 = -1e30f;
    #pragma unroll
    for (int nt = 0; nt < 8; nt++){
      mt0 = fmaxf(mt0, fmaxf(s[nt][0], s[nt][1]));
      mt1 = fmaxf(mt1, fmaxf(s[nt][2], s[nt][3]));
    }
    mt0 = fmaxf(mt0, __shfl_xor_sync(0xffffffffu, mt0, 1));
    mt0 = fmaxf(mt0, __shfl_xor_sync(0xffffffffu, mt0, 2));
    mt1 = fmaxf(mt1, __shfl_xor_sync(0xffffffffu, mt1, 1));
    mt1 = fmaxf(mt1, __shfl_xor_sync(0xffffffffu, mt1, 2));
    float mn0 = fmaxf(rm0, mt0), mn1 = fmaxf(rm1, mt1);
    float f0 = __expf(rm0 - mn0), f1 = __expf(rm1 - mn1);
    rm0 = mn0; rm1 = mn1;
    float ps0 = 0.f, ps1 = 0.f;
    #pragma unroll
    for (int nt = 0; nt < 8; nt++){
      s[nt][0] = __expf(s[nt][0] - mn0); ps0 += s[nt][0];
      s[nt][1] = __expf(s[nt][1] - mn0); ps0 += s[nt][1];
      s[nt][2] = __expf(s[nt][2] - mn1); ps1 += s[nt][2];
      s[nt][3] = __expf(s[nt][3] - mn1); ps1 += s[nt][3];
    }
    rl0 = rl0*f0 + ps0;
    rl1 = rl1*f1 + ps1;
    #pragma unroll
    for (int d = 0; d < 16; d++){
      o[d][0] *= f0; o[d][1] *= f0; o[d][2] *= f1; o[d][3] *= f1;
    }

    // ---- repack P as bf16x2 A-fragments (registers only) ----
    uint32_t pah[4][4], pal[4][4];
    #pragma unroll
    for (int k2 = 0; k2 < 4; k2++){
      split_pk(s[2*k2][0],   s[2*k2][1],   pah[k2][0], pal[k2][0]);
      split_pk(s[2*k2][2],   s[2*k2][3],   pah[k2][1], pal[k2][1]);
      split_pk(s[2*k2+1][0], s[2*k2+1][1], pah[k2][2], pal[k2][2]);
      split_pk(s[2*k2+1][2], s[2*k2+1][3], pah[k2][3], pal[k2][3]);
    }

    // ---- O += P V ----
    #pragma unroll
    for (int k2 = 0; k2 < 4; k2++){
      uint32_t vrowb = (uint32_t)(k2*16 + (lane & 7) + (((lane >> 3) & 1) << 3))*FROWB
                     + (((lane >> 4) & 1) << 4);
      #pragma unroll
      for (int dg = 0; dg < 8; dg++){
        uint32_t vh[2][2], vl[2][2];
        ldm_x4t(vH + vrowb + dg*32, vh[0][0], vh[0][1], vh[1][0], vh[1][1]);
        ldm_x4t(vL + vrowb + dg*32, vl[0][0], vl[0][1], vl[1][0], vl[1][1]);
        mma_bf(o[dg*2],     pah[k2], vh[0]);
        mma_bf(o[dg*2 + 1], pah[k2], vh[1]);
        mma_bf(o[dg*2],     pah[k2], vl[0]);
        mma_bf(o[dg*2 + 1], pah[k2], vl[1]);
        mma_bf(o[dg*2],     pal[k2], vh[0]);
        mma_bf(o[dg*2 + 1], pal[k2], vh[1]);
      }
    }

    __syncthreads();
  }

  // ---- finalize: O /= l, write bf16 hi/lo planes ----
  rl0 += __shfl_xor_sync(0xffffffffu, rl0, 1);
  rl0 += __shfl_xor_sync(0xffffffffu, rl0, 2);
  rl1 += __shfl_xor_sync(0xffffffffu, rl1, 1);
  rl1 += __shfl_xor_sync(0xffffffffu, rl1, 2);
  float inv0 = 1.f/rl0, inv1 = 1.f/rl1;
  int row = q0 + warp*16 + g;
  #pragma unroll
  for (int dg = 0; dg < 16; dg++){
    int c = h*128 + dg*8 + t4*2;
    uint32_t ph0, pl0, ph1, pl1;
    split_pk(o[dg][0]*inv0, o[dg][1]*inv0, ph0, pl0);
    split_pk(o[dg][2]*inv1, o[dg][3]*inv1, ph1, pl1);
    *reinterpret_cast<uint32_t*>(&g_AOh[(size_t)row*4096 + c])     = ph0;
    *reinterpret_cast<uint32_t*>(&g_AOl[(size_t)row*4096 + c])     = pl0;
    *reinterpret_cast<uint32_t*>(&g_AOh[(size_t)(row+8)*4096 + c]) = ph1;
    *reinterpret_cast<uint32_t*>(&g_AOl[(size_t)(row+8)*4096 + c]) = pl1;
  }
}

// =====================================================================
// launch
// =====================================================================
extern "C" void kernel_launch(void* const* d_in, const int* in_sizes, int n_in,
                              void* d_out, int out_size)
{
  (void)in_sizes; (void)n_in; (void)out_size;
  const float* x  = (const float*)d_in[0];
  const float* fc = (const float*)d_in[2];
  const float* wq = (const float*)d_in[3];
  const float* wk = (const float*)d_in[4];
  const float* wv = (const float*)d_in[5];
  const float* wo = (const float*)d_in[6];
  float* out = (float*)d_out;

  __nv_bfloat16 *Xh, *Xl, *Wth, *Wtl, *WOth, *WOtl, *AOh, *AOl;
  float *QKV;
  cudaGetSymbolAddress((void**)&Xh,   g_Xh);
  cudaGetSymbolAddress((void**)&Xl,   g_Xl);
  cudaGetSymbolAddress((void**)&Wth,  g_Wth);
  cudaGetSymbolAddress((void**)&Wtl,  g_Wtl);
  cudaGetSymbolAddress((void**)&WOth, g_WOth);
  cudaGetSymbolAddress((void**)&WOtl, g_WOtl);
  cudaGetSymbolAddress((void**)&AOh,  g_AOh);
  cudaGetSymbolAddress((void**)&AOl,  g_AOl);
  cudaGetSymbolAddress((void**)&QKV,  g_QKV);

  cudaFuncSetAttribute(gemm_ca, cudaFuncAttributeMaxDynamicSharedMemorySize, GEMM_SMEM);
  cudaFuncSetAttribute(flash_kernel, cudaFuncAttributeMaxDynamicSharedMemorySize, FLASH_SMEM);

  // conversions
  conv_x<<<8192, 256>>>(x);
  tconv<<<dim3(128, 128), 256>>>(wq, Wth,               Wtl,               4096, 4096);
  tconv<<<dim3( 32, 128), 256>>>(wk, Wth + 4096u*4096u, Wtl + 4096u*4096u, 4096, 1024);
  tconv<<<dim3( 32, 128), 256>>>(wv, Wth + 5120u*4096u, Wtl + 5120u*4096u, 4096, 1024);
  tconv<<<dim3(128, 128), 256>>>(wo, WOth,              WOtl,              4096, 4096);

  // fused QKV projection: QKV[2048,6144] = X * [wq|wk|wv]
  gemm_ca<<<dim3(48, 8), 256, GEMM_SMEM>>>(Xh, Xl, Wth, Wtl, QKV, 6144, 4096);

  // rope + plane split
  rope_split<<<24576, 256>>>(fc);

  // attention
  flash_kernel<<<dim3(16, 32), 256, FLASH_SMEM>>>();

  // output projection
  gemm_ca<<<dim3(32, 8), 256, GEMM_SMEM>>>(AOh, AOl, WOth, WOtl, out, 4096, 4096);
}

// round 8
// speedup vs baseline: 1.4027x; 1.4027x over previous
#include <cuda_runtime.h>
#include <cuda_fp16.h>
#include <cstdint>

#define DI __device__ __forceinline__

// ---------------- scratch (static device globals; no runtime alloc) ----------------
__device__ __half g_Xh [2048u*4096u];
__device__ __half g_Xl [2048u*4096u];
__device__ __half g_Wt [6144u*4096u];   // [wq|wk|wv]^T single fp16 plane
__device__ __half g_WOt[4096u*4096u];   // wo^T single fp16 plane
__device__ float  g_QKV[2048u*6144u];   // fused projection out (fp32): Q|K|V
__device__ __half g_Qh [2048u*4096u];   // post-rope, pre-scaled, hi plane
__device__ __half g_Ql [2048u*4096u];   // lo plane
__device__ __half g_K  [2048u*1024u];   // single plane
__device__ __half g_V  [2048u*1024u];   // single plane
__device__ __half g_AOh[2048u*4096u];
__device__ __half g_AOl[2048u*4096u];

// ---------------- helpers ----------------
DI uint32_t s_addr(const void* p){ return (uint32_t)__cvta_generic_to_shared(p); }

DI void ldm_x4(uint32_t a, uint32_t &r0, uint32_t &r1, uint32_t &r2, uint32_t &r3){
  asm volatile("ldmatrix.sync.aligned.m8n8.x4.shared.b16 {%0,%1,%2,%3}, [%4];\n"
               : "=r"(r0), "=r"(r1), "=r"(r2), "=r"(r3) : "r"(a));
}
DI void ldm_x4t(uint32_t a, uint32_t &r0, uint32_t &r1, uint32_t &r2, uint32_t &r3){
  asm volatile("ldmatrix.sync.aligned.m8n8.x4.trans.shared.b16 {%0,%1,%2,%3}, [%4];\n"
               : "=r"(r0), "=r"(r1), "=r"(r2), "=r"(r3) : "r"(a));
}
DI void mma_h(float c[4], const uint32_t a[4], const uint32_t b[2]){
  asm volatile("mma.sync.aligned.m16n8k16.row.col.f32.f16.f16.f32 "
               "{%0,%1,%2,%3}, {%4,%5,%6,%7}, {%8,%9}, {%0,%1,%2,%3};\n"
               : "+f"(c[0]), "+f"(c[1]), "+f"(c[2]), "+f"(c[3])
               : "r"(a[0]), "r"(a[1]), "r"(a[2]), "r"(a[3]), "r"(b[0]), "r"(b[1]));
}
DI uint32_t pk2h(__half a, __half b){
  __half2 t = __halves2half2(a, b);
  return *reinterpret_cast<uint32_t*>(&t);
}
// split 4 floats into packed fp16 hi pairs + lo (residual) pairs
DI void split4h(const float4 &v, uint32_t &h0, uint32_t &h1, uint32_t &l0, uint32_t &l1){
  __half hx = __float2half_rn(v.x);
  __half hy = __float2half_rn(v.y);
  __half hz = __float2half_rn(v.z);
  __half hw = __float2half_rn(v.w);
  h0 = pk2h(hx, hy); h1 = pk2h(hz, hw);
  l0 = pk2h(__float2half_rn(v.x - __half2float(hx)),
            __float2half_rn(v.y - __half2float(hy)));
  l1 = pk2h(__float2half_rn(v.z - __half2float(hz)),
            __float2half_rn(v.w - __half2float(hw)));
}
DI void split_pkh(float x, float y, uint32_t &h, uint32_t &l){
  __half hx = __float2half_rn(x);
  __half hy = __float2half_rn(y);
  h = pk2h(hx, hy);
  l = pk2h(__float2half_rn(x - __half2float(hx)),
           __float2half_rn(y - __half2float(hy)));
}

// ---------------- async copy primitives ----------------
DI void cp16(uint32_t saddr, const void* gaddr){
  asm volatile("cp.async.cg.shared.global [%0], [%1], 16;" :: "r"(saddr), "l"(gaddr) : "memory");
}
DI void cp_commit(){ asm volatile("cp.async.commit_group;" ::: "memory"); }
DI void cp_wait1(){ asm volatile("cp.async.wait_group 1;" ::: "memory"); }

// =====================================================================
// conversion kernels
// =====================================================================
__global__ void conv_x(const float* __restrict__ x)
{
  int i = blockIdx.x*256 + threadIdx.x;
  float4 v = reinterpret_cast<const float4*>(x)[i];
  uint32_t h0,h1,l0,l1; split4h(v, h0,h1,l0,l1);
  reinterpret_cast<uint32_t*>(g_Xh)[i*2]   = h0;
  reinterpret_cast<uint32_t*>(g_Xh)[i*2+1] = h1;
  reinterpret_cast<uint32_t*>(g_Xl)[i*2]   = l0;
  reinterpret_cast<uint32_t*>(g_Xl)[i*2+1] = l1;
}

// transpose + round: src fp32 [K,N] -> dst fp16 [N,K] (single plane)
__global__ void tconv(const float* __restrict__ src,
                      __half* __restrict__ dh, int K, int N)
{
  __shared__ float t[32][33];
  const int tid = threadIdx.x, tx = tid & 31, ty = tid >> 5;
  const int n0 = blockIdx.x << 5, k0 = blockIdx.y << 5;
  #pragma unroll
  for (int j = 0; j < 4; j++)
    t[ty + 8*j][tx] = src[(size_t)(k0 + ty + 8*j)*N + n0 + tx];
  __syncthreads();
  #pragma unroll
  for (int j = 0; j < 4; j++){
    float v = t[tx][ty + 8*j];
    dh[(size_t)(n0 + ty + 8*j)*K + k0 + tx] = __float2half_rn(v);
  }
}

// =====================================================================
// GEMM: C[M,N] = A(hi+lo fp16)[M,K] * B(fp16)[N,K]^T, fp32 acc, 2 passes.
// CTA tile 256x128x32, 512 threads (8m x 2n warps), 3-stage cp.async ring.
// smem rows: 32 fp16 (64 B) + 16 pad = 80 B (5 x 16B, odd) -> conflict-free.
// =====================================================================
#define GROWB 80
#define APLANE (256*GROWB)         // 20480 B
#define BPLANE (128*GROWB)         // 10240 B
#define GSTG   (2*APLANE + BPLANE) // 51200 B
#define GEMM_SMEM (3*GSTG)         // 153600 B

__global__ void __launch_bounds__(512, 1) gemm_ca(
    const __half* __restrict__ Ah, const __half* __restrict__ Al,
    const __half* __restrict__ Bh,
    float* __restrict__ C, int N, int K)
{
  extern __shared__ char smem[];
  const uint32_t sb = s_addr(smem);
  const int tid = threadIdx.x, lane = tid & 31, warp = tid >> 5;
  const int wm = warp >> 1, wn = warp & 1;
  const int m0 = blockIdx.y * 256, n0 = blockIdx.x * 128;

  float acc[2][8][4];
  #pragma unroll
  for (int i = 0; i < 2; i++)
    #pragma unroll
    for (int j = 0; j < 8; j++)
      #pragma unroll
      for (int k = 0; k < 4; k++) acc[i][j][k] = 0.f;

  auto issue = [&](int t){
    const uint32_t s0 = sb + (uint32_t)(t % 3)*GSTG;
    const int kb = t << 5;
    #pragma unroll
    for (int i = 0; i < 4; i++){     // A: 2 planes x 256 rows x 4 chunks = 2048 ops
      int idx = i*512 + tid;
      int p = idx >> 10, r = (idx >> 2) & 255, c = idx & 3;
      const __half* g = (p ? Al : Ah) + (size_t)(m0 + r)*K + kb + c*8;
      cp16(s0 + (uint32_t)p*APLANE + r*GROWB + c*16, g);
    }
    {                                // B: 1 plane x 128 rows x 4 chunks = 512 ops
      int idx = tid;
      int r = (idx >> 2) & 127, c = idx & 3;
      const __half* g = Bh + (size_t)(n0 + r)*K + kb + c*8;
      cp16(s0 + 2u*APLANE + r*GROWB + c*16, g);
    }
  };

  const int T = K >> 5;
  issue(0); cp_commit();
  issue(1); cp_commit();

  for (int t = 0; t < T; t++){
    cp_wait1();
    __syncthreads();
    if (t + 2 < T) issue(t + 2);
    cp_commit();
    const uint32_t s0 = sb + (uint32_t)(t % 3)*GSTG;
    const uint32_t aH = s0, aL = s0 + APLANE, bB = s0 + 2u*APLANE;
    #pragma unroll
    for (int ks = 0; ks < 2; ks++){
      uint32_t ah[2][4], al[2][4];
      #pragma unroll
      for (int wmi = 0; wmi < 2; wmi++){
        uint32_t off = (uint32_t)(wm*32 + wmi*16 + (lane & 15))*GROWB + ks*32 + ((lane >> 4) << 4);
        ldm_x4(aH + off, ah[wmi][0], ah[wmi][1], ah[wmi][2], ah[wmi][3]);
        ldm_x4(aL + off, al[wmi][0], al[wmi][1], al[wmi][2], al[wmi][3]);
      }
      const int nr = wn*64 + (lane & 7) + ((lane >> 4) << 3);
      const uint32_t ccb = ks*32 + (((lane >> 3) & 1) << 4);
      #pragma unroll
      for (int g4 = 0; g4 < 4; g4++){
        uint32_t bh[2][2];
        uint32_t off = (uint32_t)(nr + g4*16)*GROWB + ccb;
        ldm_x4(bB + off, bh[0][0], bh[0][1], bh[1][0], bh[1][1]);
        // pass-major: 4 independent accumulators between reuses
        #pragma unroll
        for (int wmi = 0; wmi < 2; wmi++)
          #pragma unroll
          for (int j = 0; j < 2; j++) mma_h(acc[wmi][g4*2 + j], ah[wmi], bh[j]);
        #pragma unroll
        for (int wmi = 0; wmi < 2; wmi++)
          #pragma unroll
          for (int j = 0; j < 2; j++) mma_h(acc[wmi][g4*2 + j], al[wmi], bh[j]);
      }
    }
    __syncthreads();
  }

  const int g = lane >> 2, tq = lane & 3;
  #pragma unroll
  for (int wmi = 0; wmi < 2; wmi++){
    int r = m0 + wm*32 + wmi*16 + g;
    #pragma unroll
    for (int nt = 0; nt < 8; nt++){
      int c = n0 + wn*64 + nt*8 + tq*2;
      float2 v0 = make_float2(acc[wmi][nt][0], acc[wmi][nt][1]);
      float2 v1 = make_float2(acc[wmi][nt][2], acc[wmi][nt][3]);
      *reinterpret_cast<float2*>(C + (size_t)r*N + c)     = v0;
      *reinterpret_cast<float2*>(C + (size_t)(r+8)*N + c) = v1;
    }
  }
}

// =====================================================================
// RoPE + convert: QKV fp32 -> Q fp16 hi/lo planes (pre-scaled), K/V fp16.
// =====================================================================
__global__ void rope_split(const float* __restrict__ fc)
{
  const int QP = 2048*2048, KP = 2048*512;
  int idx = blockIdx.x*256 + threadIdx.x;
  if (idx < QP){
    int s = idx >> 11, j = idx & 2047;
    int i = j & 63;
    float c = fc[s*128 + 2*i], d = fc[s*128 + 2*i + 1];
    const float* p = g_QKV + (size_t)s*6144 + 2*j;
    float a = p[0], b = p[1];
    const float sc = 0.08838834764831845f;   // 128^-0.5
    uint32_t hh, ll;
    split_pkh((a*c - b*d)*sc, (a*d + b*c)*sc, hh, ll);
    size_t off = (size_t)s*4096 + 2*j;
    *reinterpret_cast<uint32_t*>(&g_Qh[off]) = hh;
    *reinterpret_cast<uint32_t*>(&g_Ql[off]) = ll;
  } else if (idx < QP + KP){
    int k = idx - QP;
    int s = k >> 9, j = k & 511;
    int i = j & 63;
    float c = fc[s*128 + 2*i], d = fc[s*128 + 2*i + 1];
    const float* p = g_QKV + (size_t)s*6144 + 4096 + 2*j;
    float a = p[0], b = p[1];
    uint32_t hh = pk2h(__float2half_rn(a*c - b*d), __float2half_rn(a*d + b*c));
    *reinterpret_cast<uint32_t*>(&g_K[(size_t)s*1024 + 2*j]) = hh;
  } else {
    int k = idx - QP - KP;
    int s = k >> 9, j = k & 511;
    const float* p = g_QKV + (size_t)s*6144 + 5120 + 2*j;
    uint32_t hh = pk2h(__float2half_rn(p[0]), __float2half_rn(p[1]));
    *reinterpret_cast<uint32_t*>(&g_V[(size_t)s*1024 + 2*j]) = hh;
  }
}

// =====================================================================
// Causal flash attention. CTA = (128 q rows, 1 head), 8 warps x 16 rows.
// KV tiles of 64, 3-stage cp.async ring (K,V single fp16 planes).
// Q split fp16 hi/lo in registers; 2-pass mma for QK^T and PV.
// Row = 128 fp16 = 256 B + 16 pad = 272 B stride (17 x 16B -> conflict-free).
// =====================================================================
#define FROWB 272
#define FPLANE (64*FROWB)          // 17408 B
#define FSTAGE (2*FPLANE)          // 34816 B (K plane + V plane)
#define FLASH_SMEM (3*FSTAGE)      // 104448 B

__global__ void __launch_bounds__(256) flash_kernel()
{
  extern __shared__ char smem[];
  const uint32_t sb = s_addr(smem);
  const int tid = threadIdx.x, lane = tid & 31, warp = tid >> 5;
  const int qt = 15 - blockIdx.x;            // heavy tiles first
  const int h = blockIdx.y;
  const int q0 = qt*128, kvh = h >> 2;
  const int g = lane >> 2, t4 = lane & 3;

  // ---- stage Q planes (2 x 128 x 272 B = 69632 B, spans ring bufs 0-1) ----
  #pragma unroll
  for (int i = 0; i < 16; i++){
    int idx = i*256 + tid;
    int p = idx >> 11, r = (idx >> 4) & 127, c = idx & 15;
    const __half* src = (p ? g_Ql : g_Qh) + (size_t)(q0 + r)*4096 + h*128 + c*8;
    *reinterpret_cast<uint4*>(smem + p*(128*FROWB) + r*FROWB + c*16) =
        *reinterpret_cast<const uint4*>(src);
  }
  __syncthreads();

  uint32_t qh[8][4], ql[8][4];
  {
    const uint32_t qH = sb, qL = sb + 128*FROWB;
    uint32_t rowb = (uint32_t)(warp*16 + (lane & 15))*FROWB + ((lane >> 4) << 4);
    #pragma unroll
    for (int kk = 0; kk < 8; kk++){
      ldm_x4(qH + rowb + kk*32, qh[kk][0], qh[kk][1], qh[kk][2], qh[kk][3]);
      ldm_x4(qL + rowb + kk*32, ql[kk][0], ql[kk][1], ql[kk][2], ql[kk][3]);
    }
  }
  __syncthreads();   // all Q reads done before cp.async reuses the ring

  float o[16][4];
  #pragma unroll
  for (int i = 0; i < 16; i++){ o[i][0]=0.f; o[i][1]=0.f; o[i][2]=0.f; o[i][3]=0.f; }
  float rm0 = -1e30f, rm1 = -1e30f;
  float rl0 = 0.f,    rl1 = 0.f;

  const int nkv = qt*2 + 2;

  auto issue = [&](int kt){
    const uint32_t s0 = sb + (uint32_t)(kt % 3)*FSTAGE;
    const int kv0 = kt*64;
    #pragma unroll
    for (int i = 0; i < 8; i++){     // K,V: 2 planes x 64 rows x 16 chunks = 2048 ops
      int idx = i*256 + tid;
      int p = idx >> 10, r = (idx >> 4) & 63, c = idx & 15;
      const __half* base = p ? g_V : g_K;
      cp16(s0 + (uint32_t)p*FPLANE + r*FROWB + c*16,
           base + (size_t)(kv0 + r)*1024 + kvh*128 + c*8);
    }
  };

  issue(0); cp_commit();
  issue(1); cp_commit();

  for (int kvt = 0; kvt < nkv; kvt++){
    const int kv0 = kvt*64;
    cp_wait1();
    __syncthreads();
    if (kvt + 2 < nkv) issue(kvt + 2);   // prefetch BEFORE compute (3rd buffer free)
    cp_commit();
    const uint32_t s0 = sb + (uint32_t)(kvt % 3)*FSTAGE;
    const uint32_t kB = s0, vB = s0 + FPLANE;

    // ---- S = Q K^T (2 passes: q_hi*k + q_lo*k) ----
    float s[8][4];
    #pragma unroll
    for (int i = 0; i < 8; i++){ s[i][0]=0.f; s[i][1]=0.f; s[i][2]=0.f; s[i][3]=0.f; }
    {
      const int nr = (lane & 7) + ((lane >> 4) << 3);
      #pragma unroll
      for (int kk = 0; kk < 8; kk++){
        const uint32_t ccb = kk*32 + (((lane >> 3) & 1) << 4);
        #pragma unroll
        for (int g4 = 0; g4 < 4; g4++){
          uint32_t bh[2][2];
          uint32_t off = (uint32_t)(g4*16 + nr)*FROWB + ccb;
          ldm_x4(kB + off, bh[0][0], bh[0][1], bh[1][0], bh[1][1]);
          mma_h(s[g4*2],     qh[kk], bh[0]);
          mma_h(s[g4*2 + 1], qh[kk], bh[1]);
          mma_h(s[g4*2],     ql[kk], bh[0]);
          mma_h(s[g4*2 + 1], ql[kk], bh[1]);
        }
      }
    }

    // ---- causal mask ----
    if (kv0 + 63 > q0 + warp*16){
      #pragma unroll
      for (int nt = 0; nt < 8; nt++){
        int kvb = kv0 + nt*8 + t4*2;
        #pragma unroll
        for (int j = 0; j < 4; j++){
          int kv = kvb + (j & 1);
          int rw = q0 + warp*16 + g + ((j >> 1) << 3);
          if (kv > rw) s[nt][j] = -1e30f;
        }
      }
    }

    // ---- online softmax ----
    float mt0 = -1e30f, mt1 = -1e30f;
    #pragma unroll
    for (int nt = 0; nt < 8; nt++){
      mt0 = fmaxf(mt0, fmaxf(s[nt][0], s[nt][1]));
      mt1 = fmaxf(mt1, fmaxf(s[nt][2], s[nt][3]));
    }
    mt0 = fmaxf(mt0, __shfl_xor_sync(0xffffffffu, mt0, 1));
    mt0 = fmaxf(mt0, __shfl_xor_sync(0xffffffffu, mt0, 2));
    mt1 = fmaxf(mt1, __shfl_xor_sync(0xffffffffu, mt1, 1));
    mt1 = fmaxf(mt1, __shfl_xor_sync(0xffffffffu, mt1, 2));
    float mn0 = fmaxf(rm0, mt0), mn1 = fmaxf(rm1, mt1);
    float f0 = __expf(rm0 - mn0), f1 = __expf(rm1 - mn1);
    rm0 = mn0; rm1 = mn1;
    float ps0 = 0.f, ps1 = 0.f;
    #pragma unroll
    for (int nt = 0; nt < 8; nt++){
      s[nt][0] = __expf(s[nt][0] - mn0); ps0 += s[nt][0];
      s[nt][1] = __expf(s[nt][1] - mn0); ps0 += s[nt][1];
      s[nt][2] = __expf(s[nt][2] - mn1); ps1 += s[nt][2];
      s[nt][3] = __expf(s[nt][3] - mn1); ps1 += s[nt][3];
    }
    rl0 = rl0*f0 + ps0;
    rl1 = rl1*f1 + ps1;
    #pragma unroll
    for (int d = 0; d < 16; d++){
      o[d][0] *= f0; o[d][1] *= f0; o[d][2] *= f1; o[d][3] *= f1;
    }

    // ---- repack P as fp16x2 hi/lo A-fragments (registers only) ----
    uint32_t pah[4][4], pal[4][4];
    #pragma unroll
    for (int k2 = 0; k2 < 4; k2++){
      split_pkh(s[2*k2][0],   s[2*k2][1],   pah[k2][0], pal[k2][0]);
      split_pkh(s[2*k2][2],   s[2*k2][3],   pah[k2][1], pal[k2][1]);
      split_pkh(s[2*k2+1][0], s[2*k2+1][1], pah[k2][2], pal[k2][2]);
      split_pkh(s[2*k2+1][2], s[2*k2+1][3], pah[k2][3], pal[k2][3]);
    }

    // ---- O += P V (2 passes: p_hi*v + p_lo*v) ----
    #pragma unroll
    for (int k2 = 0; k2 < 4; k2++){
      uint32_t vrowb = (uint32_t)(k2*16 + (lane & 7) + (((lane >> 3) & 1) << 3))*FROWB
                     + (((lane >> 4) & 1) << 4);
      #pragma unroll
      for (int dg = 0; dg < 8; dg++){
        uint32_t vh[2][2];
        ldm_x4t(vB + vrowb + dg*32, vh[0][0], vh[0][1], vh[1][0], vh[1][1]);
        mma_h(o[dg*2],     pah[k2], vh[0]);
        mma_h(o[dg*2 + 1], pah[k2], vh[1]);
        mma_h(o[dg*2],     pal[k2], vh[0]);
        mma_h(o[dg*2 + 1], pal[k2], vh[1]);
      }
    }

    __syncthreads();
  }

  // ---- finalize: O /= l, write fp16 hi/lo planes ----
  rl0 += __shfl_xor_sync(0xffffffffu, rl0, 1);
  rl0 += __shfl_xor_sync(0xffffffffu, rl0, 2);
  rl1 += __shfl_xor_sync(0xffffffffu, rl1, 1);
  rl1 += __shfl_xor_sync(0xffffffffu, rl1, 2);
  float inv0 = 1.f/rl0, inv1 = 1.f/rl1;
  int row = q0 + warp*16 + g;
  #pragma unroll
  for (int dg = 0; dg < 16; dg++){
    int c = h*128 + dg*8 + t4*2;
    uint32_t ph0, pl0, ph1, pl1;
    split_pkh(o[dg][0]*inv0, o[dg][1]*inv0, ph0, pl0);
    split_pkh(o[dg][2]*inv1, o[dg][3]*inv1, ph1, pl1);
    *reinterpret_cast<uint32_t*>(&g_AOh[(size_t)row*4096 + c])     = ph0;
    *reinterpret_cast<uint32_t*>(&g_AOl[(size_t)row*4096 + c])     = pl0;
    *reinterpret_cast<uint32_t*>(&g_AOh[(size_t)(row+8)*4096 + c]) = ph1;
    *reinterpret_cast<uint32_t*>(&g_AOl[(size_t)(row+8)*4096 + c]) = pl1;
  }
}

// =====================================================================
// launch
// =====================================================================
extern "C" void kernel_launch(void* const* d_in, const int* in_sizes, int n_in,
                              void* d_out, int out_size)
{
  (void)in_sizes; (void)n_in; (void)out_size;
  const float* x  = (const float*)d_in[0];
  const float* fc = (const float*)d_in[2];
  const float* wq = (const float*)d_in[3];
  const float* wk = (const float*)d_in[4];
  const float* wv = (const float*)d_in[5];
  const float* wo = (const float*)d_in[6];
  float* out = (float*)d_out;

  __half *Xh, *Xl, *Wt, *WOt, *AOh, *AOl;
  float *QKV;
  cudaGetSymbolAddress((void**)&Xh,  g_Xh);
  cudaGetSymbolAddress((void**)&Xl,  g_Xl);
  cudaGetSymbolAddress((void**)&Wt,  g_Wt);
  cudaGetSymbolAddress((void**)&WOt, g_WOt);
  cudaGetSymbolAddress((void**)&AOh, g_AOh);
  cudaGetSymbolAddress((void**)&AOl, g_AOl);
  cudaGetSymbolAddress((void**)&QKV, g_QKV);

  cudaFuncSetAttribute(gemm_ca, cudaFuncAttributeMaxDynamicSharedMemorySize, GEMM_SMEM);
  cudaFuncSetAttribute(flash_kernel, cudaFuncAttributeMaxDynamicSharedMemorySize, FLASH_SMEM);

  // conversions
  conv_x<<<8192, 256>>>(x);
  tconv<<<dim3(128, 128), 256>>>(wq, Wt,               4096, 4096);
  tconv<<<dim3( 32, 128), 256>>>(wk, Wt + 4096u*4096u, 4096, 1024);
  tconv<<<dim3( 32, 128), 256>>>(wv, Wt + 5120u*4096u, 4096, 1024);
  tconv<<<dim3(128, 128), 256>>>(wo, WOt,              4096, 4096);

  // fused QKV projection: QKV[2048,6144] = X * [wq|wk|wv]
  gemm_ca<<<dim3(48, 8), 512, GEMM_SMEM>>>(Xh, Xl, Wt, QKV, 6144, 4096);

  // rope + fp16 conversion
  rope_split<<<24576, 256>>>(fc);

  // attention
  flash_kernel<<<dim3(16, 32), 256, FLASH_SMEM>>>();

  // output projection
  gemm_ca<<<dim3(32, 8), 512, GEMM_SMEM>>>(AOh, AOl, WOt, out, 4096, 4096);
}

// round 9
// speedup vs baseline: 2.2592x; 1.6106x over previous
#include <cuda_runtime.h>
#include <cuda_fp16.h>
#include <cstdint>

#define DI __device__ __forceinline__

// ---------------- scratch (static device globals; no runtime alloc) ----------------
__device__ __half g_X  [2048u*4096u];   // x single fp16 plane
__device__ __half g_Wt [6144u*4096u];   // [wq|wk|wv]^T single fp16 plane
__device__ __half g_WOt[4096u*4096u];   // wo^T single fp16 plane
__device__ float  g_QKV[2048u*6144u];   // fused projection out (fp32): Q|K|V
__device__ __half g_Qh [2048u*4096u];   // post-rope, pre-scaled, hi plane
__device__ __half g_Ql [2048u*4096u];   // lo plane (QK^T stays 2-pass)
__device__ __half g_K  [2048u*1024u];   // single plane
__device__ __half g_V  [2048u*1024u];   // single plane
__device__ __half g_AO [2048u*4096u];   // attention out, single plane

// ---------------- helpers ----------------
DI uint32_t s_addr(const void* p){ return (uint32_t)__cvta_generic_to_shared(p); }

DI void ldm_x4(uint32_t a, uint32_t &r0, uint32_t &r1, uint32_t &r2, uint32_t &r3){
  asm volatile("ldmatrix.sync.aligned.m8n8.x4.shared.b16 {%0,%1,%2,%3}, [%4];\n"
               : "=r"(r0), "=r"(r1), "=r"(r2), "=r"(r3) : "r"(a));
}
DI void ldm_x4t(uint32_t a, uint32_t &r0, uint32_t &r1, uint32_t &r2, uint32_t &r3){
  asm volatile("ldmatrix.sync.aligned.m8n8.x4.trans.shared.b16 {%0,%1,%2,%3}, [%4];\n"
               : "=r"(r0), "=r"(r1), "=r"(r2), "=r"(r3) : "r"(a));
}
DI void mma_h(float c[4], const uint32_t a[4], const uint32_t b[2]){
  asm volatile("mma.sync.aligned.m16n8k16.row.col.f32.f16.f16.f32 "
               "{%0,%1,%2,%3}, {%4,%5,%6,%7}, {%8,%9}, {%0,%1,%2,%3};\n"
               : "+f"(c[0]), "+f"(c[1]), "+f"(c[2]), "+f"(c[3])
               : "r"(a[0]), "r"(a[1]), "r"(a[2]), "r"(a[3]), "r"(b[0]), "r"(b[1]));
}
DI uint32_t pk2h(__half a, __half b){
  __half2 t = __halves2half2(a, b);
  return *reinterpret_cast<uint32_t*>(&t);
}
DI void split_pkh(float x, float y, uint32_t &h, uint32_t &l){
  __half hx = __float2half_rn(x);
  __half hy = __float2half_rn(y);
  h = pk2h(hx, hy);
  l = pk2h(__float2half_rn(x - __half2float(hx)),
           __float2half_rn(y - __half2float(hy)));
}

// ---------------- async copy primitives ----------------
DI void cp16(uint32_t saddr, const void* gaddr){
  asm volatile("cp.async.cg.shared.global [%0], [%1], 16;" :: "r"(saddr), "l"(gaddr) : "memory");
}
DI void cp_commit(){ asm volatile("cp.async.commit_group;" ::: "memory"); }
DI void cp_wait1(){ asm volatile("cp.async.wait_group 1;" ::: "memory"); }
DI void cp_wait2(){ asm volatile("cp.async.wait_group 2;" ::: "memory"); }

// =====================================================================
// conversion kernels
// =====================================================================
__global__ void conv_x(const float* __restrict__ x)
{
  int i = blockIdx.x*256 + threadIdx.x;   // float4 index
  float4 v = reinterpret_cast<const float4*>(x)[i];
  uint32_t h0 = pk2h(__float2half_rn(v.x), __float2half_rn(v.y));
  uint32_t h1 = pk2h(__float2half_rn(v.z), __float2half_rn(v.w));
  reinterpret_cast<uint32_t*>(g_X)[i*2]   = h0;
  reinterpret_cast<uint32_t*>(g_X)[i*2+1] = h1;
}

// transpose + round: src fp32 [K,N] -> dst fp16 [N,K]
__global__ void tconv(const float* __restrict__ src,
                      __half* __restrict__ dh, int K, int N)
{
  __shared__ float t[32][33];
  const int tid = threadIdx.x, tx = tid & 31, ty = tid >> 5;
  const int n0 = blockIdx.x << 5, k0 = blockIdx.y << 5;
  #pragma unroll
  for (int j = 0; j < 4; j++)
    t[ty + 8*j][tx] = src[(size_t)(k0 + ty + 8*j)*N + n0 + tx];
  __syncthreads();
  #pragma unroll
  for (int j = 0; j < 4; j++){
    float v = t[tx][ty + 8*j];
    dh[(size_t)(n0 + ty + 8*j)*K + k0 + tx] = __float2half_rn(v);
  }
}

// =====================================================================
// GEMM: C[M,N] = A(fp16)[M,K] * B(fp16)[N,K]^T, fp32 acc, SINGLE pass.
// CTA tile 256x128x32, 256 threads = 8 warps (4m x 2n), warp tile 64x64.
// 4-stage cp.async ring. Rows: 32 fp16 (64 B) + 16 pad = 80 B, conflict-free.
// =====================================================================
#define GROWB 80
#define APLANE (256*GROWB)         // 20480 B
#define BPLANE (128*GROWB)         // 10240 B
#define GSTG   (APLANE + BPLANE)   // 30720 B
#define GEMM_SMEM (4*GSTG)         // 122880 B

__global__ void __launch_bounds__(256, 1) gemm_ca(
    const __half* __restrict__ Ah, const __half* __restrict__ Bh,
    float* __restrict__ C, int N, int K)
{
  extern __shared__ char smem[];
  const uint32_t sb = s_addr(smem);
  const int tid = threadIdx.x, lane = tid & 31, warp = tid >> 5;
  const int wm = warp >> 1, wn = warp & 1;
  const int m0 = blockIdx.y * 256, n0 = blockIdx.x * 128;

  float acc[4][8][4];
  #pragma unroll
  for (int i = 0; i < 4; i++)
    #pragma unroll
    for (int j = 0; j < 8; j++)
      #pragma unroll
      for (int k = 0; k < 4; k++) acc[i][j][k] = 0.f;

  auto issue = [&](int t){
    const uint32_t s0 = sb + (uint32_t)(t & 3)*GSTG;
    const int kb = t << 5;
    #pragma unroll
    for (int i = 0; i < 4; i++){     // A: 256 rows x 4 chunks = 1024 ops
      int idx = i*256 + tid;
      int r = idx >> 2, c = idx & 3;
      cp16(s0 + r*GROWB + c*16, Ah + (size_t)(m0 + r)*K + kb + c*8);
    }
    #pragma unroll
    for (int i = 0; i < 2; i++){     // B: 128 rows x 4 chunks = 512 ops
      int idx = i*256 + tid;
      int r = (idx >> 2) & 127, c = idx & 3;
      cp16(s0 + APLANE + r*GROWB + c*16, Bh + (size_t)(n0 + r)*K + kb + c*8);
    }
  };

  const int T = K >> 5;
  issue(0); cp_commit();
  issue(1); cp_commit();
  issue(2); cp_commit();

  for (int t = 0; t < T; t++){
    cp_wait2();
    __syncthreads();
    if (t + 3 < T) issue(t + 3);
    cp_commit();
    const uint32_t s0 = sb + (uint32_t)(t & 3)*GSTG;
    const uint32_t aB = s0, bB = s0 + APLANE;
    #pragma unroll
    for (int ks = 0; ks < 2; ks++){
      uint32_t ah[4][4];
      #pragma unroll
      for (int wmi = 0; wmi < 4; wmi++){
        uint32_t off = (uint32_t)(wm*64 + wmi*16 + (lane & 15))*GROWB + ks*32 + ((lane >> 4) << 4);
        ldm_x4(aB + off, ah[wmi][0], ah[wmi][1], ah[wmi][2], ah[wmi][3]);
      }
      const int nr = wn*64 + (lane & 7) + ((lane >> 4) << 3);
      const uint32_t ccb = ks*32 + (((lane >> 3) & 1) << 4);
      #pragma unroll
      for (int g4 = 0; g4 < 4; g4++){
        uint32_t bh[2][2];
        uint32_t off = (uint32_t)(nr + g4*16)*GROWB + ccb;
        ldm_x4(bB + off, bh[0][0], bh[0][1], bh[1][0], bh[1][1]);
        #pragma unroll
        for (int wmi = 0; wmi < 4; wmi++)
          #pragma unroll
          for (int j = 0; j < 2; j++) mma_h(acc[wmi][g4*2 + j], ah[wmi], bh[j]);
      }
    }
    __syncthreads();
  }

  const int g = lane >> 2, tq = lane & 3;
  #pragma unroll
  for (int wmi = 0; wmi < 4; wmi++){
    int r = m0 + wm*64 + wmi*16 + g;
    #pragma unroll
    for (int nt = 0; nt < 8; nt++){
      int c = n0 + wn*64 + nt*8 + tq*2;
      float2 v0 = make_float2(acc[wmi][nt][0], acc[wmi][nt][1]);
      float2 v1 = make_float2(acc[wmi][nt][2], acc[wmi][nt][3]);
      *reinterpret_cast<float2*>(C + (size_t)r*N + c)     = v0;
      *reinterpret_cast<float2*>(C + (size_t)(r+8)*N + c) = v1;
    }
  }
}

// =====================================================================
// RoPE + convert: QKV fp32 -> Q fp16 hi/lo planes (pre-scaled), K/V fp16.
// =====================================================================
__global__ void rope_split(const float* __restrict__ fc)
{
  const int QP = 2048*2048, KP = 2048*512;
  int idx = blockIdx.x*256 + threadIdx.x;
  if (idx < QP){
    int s = idx >> 11, j = idx & 2047;
    int i = j & 63;
    float c = fc[s*128 + 2*i], d = fc[s*128 + 2*i + 1];
    const float* p = g_QKV + (size_t)s*6144 + 2*j;
    float a = p[0], b = p[1];
    const float sc = 0.08838834764831845f;   // 128^-0.5
    uint32_t hh, ll;
    split_pkh((a*c - b*d)*sc, (a*d + b*c)*sc, hh, ll);
    size_t off = (size_t)s*4096 + 2*j;
    *reinterpret_cast<uint32_t*>(&g_Qh[off]) = hh;
    *reinterpret_cast<uint32_t*>(&g_Ql[off]) = ll;
  } else if (idx < QP + KP){
    int k = idx - QP;
    int s = k >> 9, j = k & 511;
    int i = j & 63;
    float c = fc[s*128 + 2*i], d = fc[s*128 + 2*i + 1];
    const float* p = g_QKV + (size_t)s*6144 + 4096 + 2*j;
    float a = p[0], b = p[1];
    uint32_t hh = pk2h(__float2half_rn(a*c - b*d), __float2half_rn(a*d + b*c));
    *reinterpret_cast<uint32_t*>(&g_K[(size_t)s*1024 + 2*j]) = hh;
  } else {
    int k = idx - QP - KP;
    int s = k >> 9, j = k & 511;
    const float* p = g_QKV + (size_t)s*6144 + 5120 + 2*j;
    uint32_t hh = pk2h(__float2half_rn(p[0]), __float2half_rn(p[1]));
    *reinterpret_cast<uint32_t*>(&g_V[(size_t)s*1024 + 2*j]) = hh;
  }
}

// =====================================================================
// Causal flash attention. CTA = (128 q rows, 1 head), 8 warps x 16 rows.
// KV tiles of 64, 3-stage cp.async ring (K,V single fp16 planes).
// QK^T: Q hi/lo 2-pass. PV: single pass (P_hi only).
// Row = 128 fp16 = 256 B + 16 pad = 272 B stride (17 x 16B -> conflict-free).
// =====================================================================
#define FROWB 272
#define FPLANE (64*FROWB)          // 17408 B
#define FSTAGE (2*FPLANE)          // 34816 B (K plane + V plane)
#define FLASH_SMEM (3*FSTAGE)      // 104448 B

__global__ void __launch_bounds__(256) flash_kernel()
{
  extern __shared__ char smem[];
  const uint32_t sb = s_addr(smem);
  const int tid = threadIdx.x, lane = tid & 31, warp = tid >> 5;
  const int qt = 15 - blockIdx.x;            // heavy tiles first
  const int h = blockIdx.y;
  const int q0 = qt*128, kvh = h >> 2;
  const int g = lane >> 2, t4 = lane & 3;

  // ---- stage Q planes (2 x 128 x 272 B = 69632 B, spans ring bufs 0-1) ----
  #pragma unroll
  for (int i = 0; i < 16; i++){
    int idx = i*256 + tid;
    int p = idx >> 11, r = (idx >> 4) & 127, c = idx & 15;
    const __half* src = (p ? g_Ql : g_Qh) + (size_t)(q0 + r)*4096 + h*128 + c*8;
    *reinterpret_cast<uint4*>(smem + p*(128*FROWB) + r*FROWB + c*16) =
        *reinterpret_cast<const uint4*>(src);
  }
  __syncthreads();

  uint32_t qh[8][4], ql[8][4];
  {
    const uint32_t qH = sb, qL = sb + 128*FROWB;
    uint32_t rowb = (uint32_t)(warp*16 + (lane & 15))*FROWB + ((lane >> 4) << 4);
    #pragma unroll
    for (int kk = 0; kk < 8; kk++){
      ldm_x4(qH + rowb + kk*32, qh[kk][0], qh[kk][1], qh[kk][2], qh[kk][3]);
      ldm_x4(qL + rowb + kk*32, ql[kk][0], ql[kk][1], ql[kk][2], ql[kk][3]);
    }
  }
  __syncthreads();   // all Q reads done before cp.async reuses the ring

  float o[16][4];
  #pragma unroll
  for (int i = 0; i < 16; i++){ o[i][0]=0.f; o[i][1]=0.f; o[i][2]=0.f; o[i][3]=0.f; }
  float rm0 = -1e30f, rm1 = -1e30f;
  float rl0 = 0.f,    rl1 = 0.f;

  const int nkv = qt*2 + 2;

  auto issue = [&](int kt){
    const uint32_t s0 = sb + (uint32_t)(kt % 3)*FSTAGE;
    const int kv0 = kt*64;
    #pragma unroll
    for (int i = 0; i < 8; i++){     // K,V: 2 planes x 64 rows x 16 chunks = 2048 ops
      int idx = i*256 + tid;
      int p = idx >> 10, r = (idx >> 4) & 63, c = idx & 15;
      const __half* base = p ? g_V : g_K;
      cp16(s0 + (uint32_t)p*FPLANE + r*FROWB + c*16,
           base + (size_t)(kv0 + r)*1024 + kvh*128 + c*8);
    }
  };

  issue(0); cp_commit();
  issue(1); cp_commit();

  for (int kvt = 0; kvt < nkv; kvt++){
    const int kv0 = kvt*64;
    cp_wait1();
    __syncthreads();
    if (kvt + 2 < nkv) issue(kvt + 2);   // prefetch BEFORE compute (3rd buffer free)
    cp_commit();
    const uint32_t s0 = sb + (uint32_t)(kvt % 3)*FSTAGE;
    const uint32_t kB = s0, vB = s0 + FPLANE;

    // ---- S = Q K^T (2 passes: q_hi*k + q_lo*k) ----
    float s[8][4];
    #pragma unroll
    for (int i = 0; i < 8; i++){ s[i][0]=0.f; s[i][1]=0.f; s[i][2]=0.f; s[i][3]=0.f; }
    {
      const int nr = (lane & 7) + ((lane >> 4) << 3);
      #pragma unroll
      for (int kk = 0; kk < 8; kk++){
        const uint32_t ccb = kk*32 + (((lane >> 3) & 1) << 4);
        #pragma unroll
        for (int g4 = 0; g4 < 4; g4++){
          uint32_t bh[2][2];
          uint32_t off = (uint32_t)(g4*16 + nr)*FROWB + ccb;
          ldm_x4(kB + off, bh[0][0], bh[0][1], bh[1][0], bh[1][1]);
          mma_h(s[g4*2],     qh[kk], bh[0]);
          mma_h(s[g4*2 + 1], qh[kk], bh[1]);
          mma_h(s[g4*2],     ql[kk], bh[0]);
          mma_h(s[g4*2 + 1], ql[kk], bh[1]);
        }
      }
    }

    // ---- causal mask ----
    if (kv0 + 63 > q0 + warp*16){
      #pragma unroll
      for (int nt = 0; nt < 8; nt++){
        int kvb = kv0 + nt*8 + t4*2;
        #pragma unroll
        for (int j = 0; j < 4; j++){
          int kv = kvb + (j & 1);
          int rw = q0 + warp*16 + g + ((j >> 1) << 3);
          if (kv > rw) s[nt][j] = -1e30f;
        }
      }
    }

    // ---- online softmax ----
    float mt0 = -1e30f, mt1 = -1e30f;
    #pragma unroll
    for (int nt = 0; nt < 8; nt++){
      mt0 = fmaxf(mt0, fmaxf(s[nt][0], s[nt][1]));
      mt1 = fmaxf(mt1, fmaxf(s[nt][2], s[nt][3]));
    }
    mt0 = fmaxf(mt0, __shfl_xor_sync(0xffffffffu, mt0, 1));
    mt0 = fmaxf(mt0, __shfl_xor_sync(0xffffffffu, mt0, 2));
    mt1 = fmaxf(mt1, __shfl_xor_sync(0xffffffffu, mt1, 1));
    mt1 = fmaxf(mt1, __shfl_xor_sync(0xffffffffu, mt1, 2));
    float mn0 = fmaxf(rm0, mt0), mn1 = fmaxf(rm1, mt1);
    float f0 = __expf(rm0 - mn0), f1 = __expf(rm1 - mn1);
    rm0 = mn0; rm1 = mn1;
    float ps0 = 0.f, ps1 = 0.f;
    #pragma unroll
    for (int nt = 0; nt < 8; nt++){
      s[nt][0] = __expf(s[nt][0] - mn0); ps0 += s[nt][0];
      s[nt][1] = __expf(s[nt][1] - mn0); ps0 += s[nt][1];
      s[nt][2] = __expf(s[nt][2] - mn1); ps1 += s[nt][2];
      s[nt][3] = __expf(s[nt][3] - mn1); ps1 += s[nt][3];
    }
    rl0 = rl0*f0 + ps0;
    rl1 = rl1*f1 + ps1;
    #pragma unroll
    for (int d = 0; d < 16; d++){
      o[d][0] *= f0; o[d][1] *= f0; o[d][2] *= f1; o[d][3] *= f1;
    }

    // ---- repack P as fp16x2 A-fragments, hi only (registers) ----
    uint32_t pah[4][4];
    #pragma unroll
    for (int k2 = 0; k2 < 4; k2++){
      pah[k2][0] = pk2h(__float2half_rn(s[2*k2][0]),   __float2half_rn(s[2*k2][1]));
      pah[k2][1] = pk2h(__float2half_rn(s[2*k2][2]),   __float2half_rn(s[2*k2][3]));
      pah[k2][2] = pk2h(__float2half_rn(s[2*k2+1][0]), __float2half_rn(s[2*k2+1][1]));
      pah[k2][3] = pk2h(__float2half_rn(s[2*k2+1][2]), __float2half_rn(s[2*k2+1][3]));
    }

    // ---- O += P V (single pass) ----
    #pragma unroll
    for (int k2 = 0; k2 < 4; k2++){
      uint32_t vrowb = (uint32_t)(k2*16 + (lane & 7) + (((lane >> 3) & 1) << 3))*FROWB
                     + (((lane >> 4) & 1) << 4);
      #pragma unroll
      for (int dg = 0; dg < 8; dg++){
        uint32_t vh[2][2];
        ldm_x4t(vB + vrowb + dg*32, vh[0][0], vh[0][1], vh[1][0], vh[1][1]);
        mma_h(o[dg*2],     pah[k2], vh[0]);
        mma_h(o[dg*2 + 1], pah[k2], vh[1]);
      }
    }

    __syncthreads();
  }

  // ---- finalize: O /= l, write single fp16 plane ----
  rl0 += __shfl_xor_sync(0xffffffffu, rl0, 1);
  rl0 += __shfl_xor_sync(0xffffffffu, rl0, 2);
  rl1 += __shfl_xor_sync(0xffffffffu, rl1, 1);
  rl1 += __shfl_xor_sync(0xffffffffu, rl1, 2);
  float inv0 = 1.f/rl0, inv1 = 1.f/rl1;
  int row = q0 + warp*16 + g;
  #pragma unroll
  for (int dg = 0; dg < 16; dg++){
    int c = h*128 + dg*8 + t4*2;
    uint32_t ph0 = pk2h(__float2half_rn(o[dg][0]*inv0), __float2half_rn(o[dg][1]*inv0));
    uint32_t ph1 = pk2h(__float2half_rn(o[dg][2]*inv1), __float2half_rn(o[dg][3]*inv1));
    *reinterpret_cast<uint32_t*>(&g_AO[(size_t)row*4096 + c])     = ph0;
    *reinterpret_cast<uint32_t*>(&g_AO[(size_t)(row+8)*4096 + c]) = ph1;
  }
}

// =====================================================================
// launch
// =====================================================================
extern "C" void kernel_launch(void* const* d_in, const int* in_sizes, int n_in,
                              void* d_out, int out_size)
{
  (void)in_sizes; (void)n_in; (void)out_size;
  const float* x  = (const float*)d_in[0];
  const float* fc = (const float*)d_in[2];
  const float* wq = (const float*)d_in[3];
  const float* wk = (const float*)d_in[4];
  const float* wv = (const float*)d_in[5];
  const float* wo = (const float*)d_in[6];
  float* out = (float*)d_out;

  __half *X, *Wt, *WOt, *AO;
  float *QKV;
  cudaGetSymbolAddress((void**)&X,   g_X);
  cudaGetSymbolAddress((void**)&Wt,  g_Wt);
  cudaGetSymbolAddress((void**)&WOt, g_WOt);
  cudaGetSymbolAddress((void**)&AO,  g_AO);
  cudaGetSymbolAddress((void**)&QKV, g_QKV);

  cudaFuncSetAttribute(gemm_ca, cudaFuncAttributeMaxDynamicSharedMemorySize, GEMM_SMEM);
  cudaFuncSetAttribute(flash_kernel, cudaFuncAttributeMaxDynamicSharedMemorySize, FLASH_SMEM);

  // conversions
  conv_x<<<8192, 256>>>(x);
  tconv<<<dim3(128, 128), 256>>>(wq, Wt,               4096, 4096);
  tconv<<<dim3( 32, 128), 256>>>(wk, Wt + 4096u*4096u, 4096, 1024);
  tconv<<<dim3( 32, 128), 256>>>(wv, Wt + 5120u*4096u, 4096, 1024);
  tconv<<<dim3(128, 128), 256>>>(wo, WOt,              4096, 4096);

  // fused QKV projection: QKV[2048,6144] = X * [wq|wk|wv]
  gemm_ca<<<dim3(48, 8), 256, GEMM_SMEM>>>(X, Wt, QKV, 6144, 4096);

  // rope + fp16 conversion
  rope_split<<<24576, 256>>>(fc);

  // attention
  flash_kernel<<<dim3(16, 32), 256, FLASH_SMEM>>>();

  // output projection
  gemm_ca<<<dim3(32, 8), 256, GEMM_SMEM>>>(AO, WOt, out, 4096, 4096);
}